// round 1
// baseline (speedup 1.0000x reference)
#include <cuda_runtime.h>
#include <math.h>

// Problem constants: B=8, S=256, N=256, C=64, NH=8, D=2048, 4C=256
// P layout: [b][s][n][ch] = ((b*256+s)*256+n)*256+ch   (134,217,728 floats, 512MB)
//   q  rows n in [0,64):    head h -> n in [h*8, h*8+8)
//   k  rows n in [64,128)
//   vH rows n in [128,192)
//   vV rows n in [192,256)
__device__ float g_P[134217728];
__device__ float g_AH[4194304];   // [b*8+h][s][t]
__device__ float g_AV[4194304];

// ---------------------------------------------------------------------------
// Kernel 1: QKV projection (X(256x64) @ W^T(64x256) + bias) per (b,s) tile,
// fused q/k row-group L2 normalization (groups of 8 n-rows = one head vector).
// grid (2048, 2): blockIdx.x = b*256+s, blockIdx.y = which 128-row half.
// block (32,16) = 512 threads, 8x8 register tile each.
// ---------------------------------------------------------------------------
__global__ void __launch_bounds__(512, 1)
k_qkv(const float* __restrict__ x, const float* __restrict__ w,
      const float* __restrict__ bias)
{
    extern __shared__ float sm[];
    float* Xs = sm;              // [64][129]  transposed X tile (k-major)
    float* Ws = sm + 64 * 129;   // [64][256]  transposed W (k-major)
    __shared__ float snorm[16];

    const int bs   = blockIdx.x;
    const int half = blockIdx.y;
    const int b = bs >> 8, s = bs & 255;
    const int n0 = half << 7;
    const int tx = threadIdx.x, ty = threadIdx.y;
    const int tid = ty * 32 + tx;

    // load X tile (128 rows x 64) transposed into smem
    {
        const float* xg = x + (((size_t)(b * 256 + s) * 256 + n0) * 64);
        int row = tid >> 2;
        int kp  = (tid & 3) << 4;
        const float* src = xg + row * 64 + kp;
        #pragma unroll
        for (int u = 0; u < 16; u += 4) {
            float4 v = *(const float4*)(src + u);
            Xs[(kp + u + 0) * 129 + row] = v.x;
            Xs[(kp + u + 1) * 129 + row] = v.y;
            Xs[(kp + u + 2) * 129 + row] = v.z;
            Xs[(kp + u + 3) * 129 + row] = v.w;
        }
    }
    // load W (256 x 64) transposed into smem: Ws[k][ch]
    {
        int ch = tid >> 1;
        int kp = (tid & 1) << 5;
        const float* src = w + ch * 64 + kp;
        #pragma unroll
        for (int u = 0; u < 32; u += 4) {
            float4 v = *(const float4*)(src + u);
            Ws[(kp + u + 0) * 256 + ch] = v.x;
            Ws[(kp + u + 1) * 256 + ch] = v.y;
            Ws[(kp + u + 2) * 256 + ch] = v.z;
            Ws[(kp + u + 3) * 256 + ch] = v.w;
        }
    }
    __syncthreads();

    float acc[8][8];
    {
        float bj[8];
        #pragma unroll
        for (int j = 0; j < 8; j++) bj[j] = bias[tx * 8 + j];
        #pragma unroll
        for (int i = 0; i < 8; i++)
            #pragma unroll
            for (int j = 0; j < 8; j++) acc[i][j] = bj[j];
    }

    #pragma unroll 4
    for (int k = 0; k < 64; k++) {
        float a[8];
        #pragma unroll
        for (int i = 0; i < 8; i++) a[i] = Xs[k * 129 + ty * 8 + i];
        float4 w0 = *(float4*)(Ws + k * 256 + tx * 8);
        float4 w1 = *(float4*)(Ws + k * 256 + tx * 8 + 4);
        float wv[8] = {w0.x, w0.y, w0.z, w0.w, w1.x, w1.y, w1.z, w1.w};
        #pragma unroll
        for (int i = 0; i < 8; i++)
            #pragma unroll
            for (int j = 0; j < 8; j++)
                acc[i][j] = fmaf(a[i], wv[j], acc[i][j]);
    }

    float scale = 1.0f;
    if (half == 0) {
        // thread ty owns rows ty*8..ty*8+8 == exactly one q/k head vector
        float ss = 0.f;
        #pragma unroll
        for (int i = 0; i < 8; i++)
            #pragma unroll
            for (int j = 0; j < 8; j++) ss += acc[i][j] * acc[i][j];
        #pragma unroll
        for (int off = 16; off > 0; off >>= 1)
            ss += __shfl_xor_sync(0xffffffffu, ss, off);
        if (tx == 0) snorm[ty] = ss;
        __syncthreads();
        float nrm = sqrtf(snorm[ty]);
        scale = 1.0f / fmaxf(nrm, 1e-12f);
    }

    float* og = g_P + ((size_t)(b * 256 + s) * 256 + n0 + ty * 8) * 256 + tx * 8;
    #pragma unroll
    for (int i = 0; i < 8; i++) {
        float4 v0 = make_float4(acc[i][0] * scale, acc[i][1] * scale,
                                acc[i][2] * scale, acc[i][3] * scale);
        float4 v1 = make_float4(acc[i][4] * scale, acc[i][5] * scale,
                                acc[i][6] * scale, acc[i][7] * scale);
        *(float4*)(og + (size_t)i * 256)     = v0;
        *(float4*)(og + (size_t)i * 256 + 4) = v1;
    }
}

// ---------------------------------------------------------------------------
// Kernel 2: sim = Qn @ Kn^T (256x2048 . 2048x256) per (b,h), then dual
// softmax (temperature1 -> A_H, temperature2 -> A_V).
// grid (64, 2): blockIdx.x = b*8+h, blockIdx.y = s-half.
// ---------------------------------------------------------------------------
__global__ void __launch_bounds__(512, 1)
k_attn(const float* __restrict__ t1g, const float* __restrict__ t2g)
{
    __shared__ float Qs[128 * 16];   // [s][dk]
    __shared__ float Ks[16 * 256];   // [dk][t]  (transposed)

    const int bh = blockIdx.x;
    const int b = bh >> 3, h = bh & 7;
    const int s0 = blockIdx.y << 7;
    const int tx = threadIdx.x, ty = threadIdx.y;
    const int tid = ty * 32 + tx;

    const float* qb = g_P + (size_t)b * 16777216 + h * 2048;
    const float* kb = qb + 16384;   // +64 n-rows

    float acc[8][8];
    #pragma unroll
    for (int i = 0; i < 8; i++)
        #pragma unroll
        for (int j = 0; j < 8; j++) acc[i][j] = 0.f;

    for (int d0 = 0; d0 < 2048; d0 += 16) {
        {
            int sr = tid >> 2;
            int kp = (tid & 3) << 2;
            float4 v = *(const float4*)(qb + (size_t)(s0 + sr) * 65536 + d0 + kp);
            *(float4*)(Qs + sr * 16 + kp) = v;
        }
        {
            int t  = tid >> 1;
            int kp = (tid & 1) << 3;
            const float* src = kb + (size_t)t * 65536 + d0 + kp;
            float4 v0 = *(const float4*)(src);
            float4 v1 = *(const float4*)(src + 4);
            Ks[(kp + 0) * 256 + t] = v0.x;
            Ks[(kp + 1) * 256 + t] = v0.y;
            Ks[(kp + 2) * 256 + t] = v0.z;
            Ks[(kp + 3) * 256 + t] = v0.w;
            Ks[(kp + 4) * 256 + t] = v1.x;
            Ks[(kp + 5) * 256 + t] = v1.y;
            Ks[(kp + 6) * 256 + t] = v1.z;
            Ks[(kp + 7) * 256 + t] = v1.w;
        }
        __syncthreads();
        #pragma unroll
        for (int kk = 0; kk < 16; kk++) {
            float a[8];
            #pragma unroll
            for (int i = 0; i < 8; i++) a[i] = Qs[(ty * 8 + i) * 16 + kk];
            float4 k0 = *(float4*)(Ks + kk * 256 + tx * 8);
            float4 k1 = *(float4*)(Ks + kk * 256 + tx * 8 + 4);
            float kv[8] = {k0.x, k0.y, k0.z, k0.w, k1.x, k1.y, k1.z, k1.w};
            #pragma unroll
            for (int i = 0; i < 8; i++)
                #pragma unroll
                for (int j = 0; j < 8; j++)
                    acc[i][j] = fmaf(a[i], kv[j], acc[i][j]);
        }
        __syncthreads();
    }

    const float t1 = t1g[h];
    const float t2 = t2g[h];
    float* AH = g_AH + (size_t)bh * 65536;
    float* AV = g_AV + (size_t)bh * 65536;

    #pragma unroll
    for (int i = 0; i < 8; i++) {
        const int srow = s0 + ty * 8 + i;
        // ---- softmax H ----
        {
            float mx = -3.0e38f;
            #pragma unroll
            for (int j = 0; j < 8; j++) mx = fmaxf(mx, acc[i][j] * t1);
            #pragma unroll
            for (int off = 16; off > 0; off >>= 1)
                mx = fmaxf(mx, __shfl_xor_sync(0xffffffffu, mx, off));
            float e[8]; float sum = 0.f;
            #pragma unroll
            for (int j = 0; j < 8; j++) { e[j] = __expf(acc[i][j] * t1 - mx); sum += e[j]; }
            #pragma unroll
            for (int off = 16; off > 0; off >>= 1)
                sum += __shfl_xor_sync(0xffffffffu, sum, off);
            float inv = 1.0f / sum;
            float* dst = AH + (size_t)srow * 256 + tx * 8;
            *(float4*)(dst)     = make_float4(e[0]*inv, e[1]*inv, e[2]*inv, e[3]*inv);
            *(float4*)(dst + 4) = make_float4(e[4]*inv, e[5]*inv, e[6]*inv, e[7]*inv);
        }
        // ---- softmax V ----
        {
            float mx = -3.0e38f;
            #pragma unroll
            for (int j = 0; j < 8; j++) mx = fmaxf(mx, acc[i][j] * t2);
            #pragma unroll
            for (int off = 16; off > 0; off >>= 1)
                mx = fmaxf(mx, __shfl_xor_sync(0xffffffffu, mx, off));
            float e[8]; float sum = 0.f;
            #pragma unroll
            for (int j = 0; j < 8; j++) { e[j] = __expf(acc[i][j] * t2 - mx); sum += e[j]; }
            #pragma unroll
            for (int off = 16; off > 0; off >>= 1)
                sum += __shfl_xor_sync(0xffffffffu, sum, off);
            float inv = 1.0f / sum;
            float* dst = AV + (size_t)srow * 256 + tx * 8;
            *(float4*)(dst)     = make_float4(e[0]*inv, e[1]*inv, e[2]*inv, e[3]*inv);
            *(float4*)(dst + 4) = make_float4(e[4]*inv, e[5]*inv, e[6]*inv, e[7]*inv);
        }
    }
}

// ---------------------------------------------------------------------------
// Kernel 3: xsum = A_H @ V_H + A_V @ V_Vfinal  (per (b,h), 256x2048),
// fused 64->64 output projection epilogue, writes d_out directly.
// grid (64, 16): blockIdx.x = b*8+h; blockIdx.y: bit0 = s-half, bits[1..3] =
// d-group (256 d-cols = 4 output n-rows "j").
// ---------------------------------------------------------------------------
__global__ void __launch_bounds__(512, 1)
k_av(const float* __restrict__ pw, const float* __restrict__ pb,
     float* __restrict__ out)
{
    extern __shared__ float sm[];
    float* AHs = sm;          // [128][16]
    float* AVs = sm + 2048;   // [128][16]
    float* Vhs = sm + 4096;   // [16][256]
    float* Vvs = sm + 8192;   // [16][256]

    const int bh = blockIdx.x;
    const int b = bh >> 3, h = bh & 7;
    const int tile = blockIdx.y;
    const int s0 = (tile & 1) << 7;
    const int dg = tile >> 1;        // 0..7
    const int d0 = dg << 8;          // d offset within head (0..2048)
    const int j0 = dg << 2;          // output n-row group base (within head)

    const int tx = threadIdx.x, ty = threadIdx.y;
    const int tid = ty * 32 + tx;

    const float* AHb = g_AH + (size_t)bh * 65536 + (size_t)s0 * 256;
    const float* AVb = g_AV + (size_t)bh * 65536 + (size_t)s0 * 256;
    // V_H[t, d] = P[b, t, 128 + h*8 + d/256, d%256]  (contiguous 2048/row)
    const float* vh = g_P + (size_t)b * 16777216 + 32768 + h * 2048 + d0;
    // V_Vfinal[t, j*64+c] = P[b, h*32+j, 192 + t/4, (t%4)*64 + c]
    const float* vv = g_P + (size_t)b * 16777216 + (size_t)(h * 32 + j0) * 65536 + 49152;

    float acc[8][8];
    #pragma unroll
    for (int i = 0; i < 8; i++)
        #pragma unroll
        for (int j = 0; j < 8; j++) acc[i][j] = 0.f;

    for (int t0 = 0; t0 < 256; t0 += 16) {
        {
            int sr = tid >> 2;
            int tp = (tid & 3) << 2;
            *(float4*)(AHs + sr * 16 + tp) =
                *(const float4*)(AHb + (size_t)sr * 256 + t0 + tp);
            *(float4*)(AVs + sr * 16 + tp) =
                *(const float4*)(AVb + (size_t)sr * 256 + t0 + tp);
        }
        {
            int tt = tid >> 5;
            int dp = (tid & 31) << 3;
            const float* src = vh + (size_t)(t0 + tt) * 65536 + dp;
            *(float4*)(Vhs + tt * 256 + dp)     = *(const float4*)(src);
            *(float4*)(Vhs + tt * 256 + dp + 4) = *(const float4*)(src + 4);
            int jj = dp >> 6, c = dp & 63;
            const float* src2 = vv + (size_t)jj * 65536 + (t0 + tt) * 64 + c;
            *(float4*)(Vvs + tt * 256 + dp)     = *(const float4*)(src2);
            *(float4*)(Vvs + tt * 256 + dp + 4) = *(const float4*)(src2 + 4);
        }
        __syncthreads();
        #pragma unroll
        for (int tt = 0; tt < 16; tt++) {
            float a1[8], a2[8];
            #pragma unroll
            for (int i = 0; i < 8; i++) {
                a1[i] = AHs[(ty * 8 + i) * 16 + tt];
                a2[i] = AVs[(ty * 8 + i) * 16 + tt];
            }
            float4 u0 = *(float4*)(Vhs + tt * 256 + tx * 8);
            float4 u1 = *(float4*)(Vhs + tt * 256 + tx * 8 + 4);
            float4 w0 = *(float4*)(Vvs + tt * 256 + tx * 8);
            float4 w1 = *(float4*)(Vvs + tt * 256 + tx * 8 + 4);
            float v1[8] = {u0.x, u0.y, u0.z, u0.w, u1.x, u1.y, u1.z, u1.w};
            float v2[8] = {w0.x, w0.y, w0.z, w0.w, w1.x, w1.y, w1.z, w1.w};
            #pragma unroll
            for (int i = 0; i < 8; i++)
                #pragma unroll
                for (int j = 0; j < 8; j++) {
                    acc[i][j] = fmaf(a1[i], v1[j], acc[i][j]);
                    acc[i][j] = fmaf(a2[i], v2[j], acc[i][j]);
                }
        }
        __syncthreads();
    }

    // ---------------- fused projection epilogue ----------------
    float* xs  = sm;                 // [128][256]   xsum
    float* pwt = sm + 32768;         // [64][64]     proj_w transposed [c'][c_out]
    float* pbs = sm + 32768 + 4096;  // [64]

    #pragma unroll
    for (int i = 0; i < 8; i++) {
        *(float4*)(xs + (ty * 8 + i) * 256 + tx * 8) =
            make_float4(acc[i][0], acc[i][1], acc[i][2], acc[i][3]);
        *(float4*)(xs + (ty * 8 + i) * 256 + tx * 8 + 4) =
            make_float4(acc[i][4], acc[i][5], acc[i][6], acc[i][7]);
    }
    if (tid < 64) pbs[tid] = pb[tid];
    {
        int co = tid >> 3;
        int cp = (tid & 7) << 3;
        const float* src = pw + co * 64 + cp;
        float4 v0 = *(const float4*)(src);
        float4 v1 = *(const float4*)(src + 4);
        pwt[(cp + 0) * 64 + co] = v0.x;
        pwt[(cp + 1) * 64 + co] = v0.y;
        pwt[(cp + 2) * 64 + co] = v0.z;
        pwt[(cp + 3) * 64 + co] = v0.w;
        pwt[(cp + 4) * 64 + co] = v1.x;
        pwt[(cp + 5) * 64 + co] = v1.y;
        pwt[(cp + 6) * 64 + co] = v1.z;
        pwt[(cp + 7) * 64 + co] = v1.w;
    }
    __syncthreads();

    const int jl  = tx >> 3;         // local j within the 4-j group
    const int co0 = (tx & 7) << 3;   // c_out base
    float acc2[8][8];
    #pragma unroll
    for (int i = 0; i < 8; i++)
        #pragma unroll
        for (int jc = 0; jc < 8; jc++) acc2[i][jc] = pbs[co0 + jc];

    #pragma unroll 4
    for (int cp = 0; cp < 64; cp++) {
        float xv[8];
        #pragma unroll
        for (int i = 0; i < 8; i++) xv[i] = xs[(ty * 8 + i) * 256 + jl * 64 + cp];
        float4 w0 = *(float4*)(pwt + cp * 64 + co0);
        float4 w1 = *(float4*)(pwt + cp * 64 + co0 + 4);
        float wv[8] = {w0.x, w0.y, w0.z, w0.w, w1.x, w1.y, w1.z, w1.w};
        #pragma unroll
        for (int i = 0; i < 8; i++)
            #pragma unroll
            for (int jc = 0; jc < 8; jc++)
                acc2[i][jc] = fmaf(xv[i], wv[jc], acc2[i][jc]);
    }

    #pragma unroll
    for (int i = 0; i < 8; i++) {
        float* og = out + ((size_t)(b * 256 + s0 + ty * 8 + i) * 256
                           + h * 32 + j0 + jl) * 64 + co0;
        *(float4*)(og)     = make_float4(acc2[i][0], acc2[i][1], acc2[i][2], acc2[i][3]);
        *(float4*)(og + 4) = make_float4(acc2[i][4], acc2[i][5], acc2[i][6], acc2[i][7]);
    }
}

// ---------------------------------------------------------------------------
extern "C" void kernel_launch(void* const* d_in, const int* in_sizes, int n_in,
                              void* d_out, int out_size)
{
    const float* x      = (const float*)d_in[0];
    const float* qkv_w  = (const float*)d_in[1];
    const float* qkv_b  = (const float*)d_in[2];
    const float* proj_w = (const float*)d_in[3];
    const float* proj_b = (const float*)d_in[4];
    const float* t1     = (const float*)d_in[5];
    const float* t2     = (const float*)d_in[6];
    float* out = (float*)d_out;

    const int smem1 = (64 * 129 + 64 * 256) * (int)sizeof(float);          // ~96.3 KB
    const int smem3 = (32768 + 4096 + 64) * (int)sizeof(float);            // ~144.3 KB

    cudaFuncSetAttribute((const void*)k_qkv,
                         cudaFuncAttributeMaxDynamicSharedMemorySize, smem1);
    cudaFuncSetAttribute((const void*)k_av,
                         cudaFuncAttributeMaxDynamicSharedMemorySize, smem3);

    dim3 blk(32, 16);
    k_qkv<<<dim3(2048, 2), blk, smem1>>>(x, qkv_w, qkv_b);
    k_attn<<<dim3(64, 2), blk>>>(t1, t2);
    k_av<<<dim3(64, 16), blk, smem3>>>(proj_w, proj_b, out);
}